// round 4
// baseline (speedup 1.0000x reference)
#include <cuda_runtime.h>

#define IMG    144
#define NTOK   1296           // tokens per batch
#define EDIM   16
#define BATCH  4
#define NJ     6              // j-chunks
#define JCHUNK 216            // 1296 / 6
#define QT     11             // ceil(1296/128) query tiles
#define THREADS 128

// ---- device scratch (no allocations allowed) ----
__device__ float g_maxpart[81];
__device__ float g_inv2;                                   // 1 / x_max^2
__device__ float g_ps  [NJ][BATCH][NTOK];                  // partial softmax sums
__device__ float g_pacc[NJ][BATCH][NTOK][EDIM];            // partial weighted sums

__device__ __forceinline__ float ex2(float x) {
    float r;
    asm("ex2.approx.ftz.f32 %0, %1;" : "=f"(r) : "f"(x));
    return r;
}

// ---------------- Kernel 1: per-block max (81 blocks x 256 thr x 1 float4 = 82944 elems, exact)
__global__ __launch_bounds__(256) void kmax1(const float* __restrict__ x) {
    __shared__ float sm[8];
    const int t = threadIdx.x;
    float4 v = ((const float4*)x)[blockIdx.x * 256 + t];
    float m = fmaxf(fmaxf(v.x, v.y), fmaxf(v.z, v.w));
    #pragma unroll
    for (int o = 16; o; o >>= 1) m = fmaxf(m, __shfl_xor_sync(0xffffffffu, m, o));
    if ((t & 31) == 0) sm[t >> 5] = m;
    __syncthreads();
    if (t < 32) {
        float w = (t < 8) ? sm[t] : -1e30f;
        #pragma unroll
        for (int o = 4; o; o >>= 1) w = fmaxf(w, __shfl_xor_sync(0xffffffffu, w, o));
        if (t == 0) g_maxpart[blockIdx.x] = w;
    }
}

// ---------------- Kernel 2: reduce 81 partial maxes -> g_inv2
__global__ __launch_bounds__(128) void kmax2() {
    const int t = threadIdx.x;
    __shared__ float sm[4];
    float m = (t < 81) ? g_maxpart[t] : -1e30f;
    #pragma unroll
    for (int o = 16; o; o >>= 1) m = fmaxf(m, __shfl_xor_sync(0xffffffffu, m, o));
    if ((t & 31) == 0) sm[t >> 5] = m;
    __syncthreads();
    if (t == 0) {
        float w = fmaxf(fmaxf(sm[0], sm[1]), fmaxf(sm[2], sm[3]));
        g_inv2 = 1.0f / (w * w);
    }
}

// ---------------- Kernel 3: attention partials over one j-chunk
// grid: (NJ, QT, BATCH), 128 threads. Thread owns one query i; k rows broadcast from smem.
__global__ __launch_bounds__(THREADS) void kattn(const float* __restrict__ x) {
    const int jc = blockIdx.x;
    const int qt = blockIdx.y;
    const int b  = blockIdx.z;

    __shared__ float4 sk[JCHUNK * 4];   // 216 rows x 16 floats
    __shared__ float  skk[JCHUNK];      // precomputed -||k||^2 * log2e/16 * inv2

    const float inv2  = g_inv2;
    const float c_dot = inv2 * 0.18033688011112042f;   // 2*log2(e)/16
    const float c_sq  = -inv2 * 0.09016844005556021f;  // -log2(e)/16

    const float*  xb  = x + (size_t)b * NTOK * EDIM;
    const float4* src = (const float4*)(xb + jc * JCHUNK * EDIM);

    for (int idx = threadIdx.x; idx < JCHUNK * 4; idx += THREADS) sk[idx] = src[idx];
    __syncthreads();

    for (int j = threadIdx.x; j < JCHUNK; j += THREADS) {
        float4 a = sk[4*j], c = sk[4*j+1], d = sk[4*j+2], e = sk[4*j+3];
        float kk = a.x*a.x + a.y*a.y + a.z*a.z + a.w*a.w
                 + c.x*c.x + c.y*c.y + c.z*c.z + c.w*c.w
                 + d.x*d.x + d.y*d.y + d.z*d.z + d.w*d.w
                 + e.x*e.x + e.y*e.y + e.z*e.z + e.w*e.w;
        skk[j] = kk * c_sq;
    }
    __syncthreads();

    const int i = qt * THREADS + threadIdx.x;
    if (i >= NTOK) return;   // last tile: 16 live threads; safe (no syncs below)

    float q[16];
    {
        const float4* qp = (const float4*)(xb + i * EDIM);
        float4 t0 = qp[0], t1 = qp[1], t2 = qp[2], t3 = qp[3];
        q[0]=t0.x; q[1]=t0.y; q[2]=t0.z; q[3]=t0.w;
        q[4]=t1.x; q[5]=t1.y; q[6]=t1.z; q[7]=t1.w;
        q[8]=t2.x; q[9]=t2.y; q[10]=t2.z; q[11]=t2.w;
        q[12]=t3.x; q[13]=t3.y; q[14]=t3.z; q[15]=t3.w;
    }
    float qq = 0.f;
    #pragma unroll
    for (int d = 0; d < 16; d++) qq = fmaf(q[d], q[d], qq);
    const float qqc = qq * c_sq;

    float s = 0.f;
    float acc[16];
    #pragma unroll
    for (int d = 0; d < 16; d++) acc[d] = 0.f;

    #pragma unroll 4
    for (int j = 0; j < JCHUNK; j++) {
        float4 k0 = sk[4*j], k1 = sk[4*j+1], k2 = sk[4*j+2], k3 = sk[4*j+3];
        // 4 independent partial dots for ILP
        float d0 = q[0]*k0.x;  d0 = fmaf(q[1], k0.y, d0);  d0 = fmaf(q[2], k0.z, d0);  d0 = fmaf(q[3], k0.w, d0);
        float d1 = q[4]*k1.x;  d1 = fmaf(q[5], k1.y, d1);  d1 = fmaf(q[6], k1.z, d1);  d1 = fmaf(q[7], k1.w, d1);
        float d2 = q[8]*k2.x;  d2 = fmaf(q[9], k2.y, d2);  d2 = fmaf(q[10],k2.z, d2);  d2 = fmaf(q[11],k2.w, d2);
        float d3 = q[12]*k3.x; d3 = fmaf(q[13],k3.y, d3);  d3 = fmaf(q[14],k3.z, d3);  d3 = fmaf(q[15],k3.w, d3);
        float dot = (d0 + d1) + (d2 + d3);

        float p = ex2(fmaf(dot, c_dot, qqc + skk[j]));   // exp(-mean((q-k)^2)/xmax^2)
        s += p;

        acc[0]  = fmaf(p, k0.x, acc[0]);  acc[1]  = fmaf(p, k0.y, acc[1]);
        acc[2]  = fmaf(p, k0.z, acc[2]);  acc[3]  = fmaf(p, k0.w, acc[3]);
        acc[4]  = fmaf(p, k1.x, acc[4]);  acc[5]  = fmaf(p, k1.y, acc[5]);
        acc[6]  = fmaf(p, k1.z, acc[6]);  acc[7]  = fmaf(p, k1.w, acc[7]);
        acc[8]  = fmaf(p, k2.x, acc[8]);  acc[9]  = fmaf(p, k2.y, acc[9]);
        acc[10] = fmaf(p, k2.z, acc[10]); acc[11] = fmaf(p, k2.w, acc[11]);
        acc[12] = fmaf(p, k3.x, acc[12]); acc[13] = fmaf(p, k3.y, acc[13]);
        acc[14] = fmaf(p, k3.z, acc[14]); acc[15] = fmaf(p, k3.w, acc[15]);
    }

    g_ps[jc][b][i] = s;
    float4* pa = (float4*)g_pacc[jc][b][i];
    pa[0] = make_float4(acc[0],  acc[1],  acc[2],  acc[3]);
    pa[1] = make_float4(acc[4],  acc[5],  acc[6],  acc[7]);
    pa[2] = make_float4(acc[8],  acc[9],  acc[10], acc[11]);
    pa[3] = make_float4(acc[12], acc[13], acc[14], acc[15]);
}

// ---------------- Kernel 4: combine partials, divide, apply fold permutation
__global__ __launch_bounds__(THREADS) void kfinal(float* __restrict__ out) {
    const int g = blockIdx.x * THREADS + threadIdx.x;
    if (g >= BATCH * NTOK) return;
    const int b = g / NTOK;
    const int i = g % NTOK;

    float s = 0.f;
    float acc[16];
    #pragma unroll
    for (int d = 0; d < 16; d++) acc[d] = 0.f;

    #pragma unroll
    for (int jc = 0; jc < NJ; jc++) {
        s += g_ps[jc][b][i];
        const float4* pa = (const float4*)g_pacc[jc][b][i];
        float4 v0 = pa[0], v1 = pa[1], v2 = pa[2], v3 = pa[3];
        acc[0]+=v0.x;  acc[1]+=v0.y;  acc[2]+=v0.z;  acc[3]+=v0.w;
        acc[4]+=v1.x;  acc[5]+=v1.y;  acc[6]+=v1.z;  acc[7]+=v1.w;
        acc[8]+=v2.x;  acc[9]+=v2.y;  acc[10]+=v2.z; acc[11]+=v2.w;
        acc[12]+=v3.x; acc[13]+=v3.y; acc[14]+=v3.z; acc[15]+=v3.w;
    }

    const float r = 1.0f / s;   // s >= 1 always (self term exp(0))
    const int by = i / 36, bx = i % 36;
    float* ob = out + (size_t)b * IMG * IMG;
    #pragma unroll
    for (int ky = 0; ky < 4; ky++) {
        float4 v = make_float4(acc[ky*4+0]*r, acc[ky*4+1]*r, acc[ky*4+2]*r, acc[ky*4+3]*r);
        *(float4*)(ob + (by*4 + ky) * IMG + bx*4) = v;
    }
}

extern "C" void kernel_launch(void* const* d_in, const int* in_sizes, int n_in,
                              void* d_out, int out_size) {
    const float* x = (const float*)d_in[0];
    float* out = (float*)d_out;

    kmax1<<<81, 256>>>(x);
    kmax2<<<1, 128>>>();
    kattn<<<dim3(NJ, QT, BATCH), THREADS>>>(x);
    kfinal<<<(BATCH * NTOK + THREADS - 1) / THREADS, THREADS>>>(out);
}